// round 17
// baseline (speedup 1.0000x reference)
#include <cuda_runtime.h>
#include <cuda_fp16.h>

#define B 8
#define S 512
#define E 64
#define H 8
#define NT 1024

// ---- dynamic smem layout (bytes) ------------------------------------------
// Phases A/B: K only. Phase C overlays W/bias/Cs onto the (dead) K region.
#define KS_STRIDE 8208                 // per-head: 512*16B rows + 16B pad
#define KS_BYTES  (8 * KS_STRIDE)      // 65664 -> 2 blocks/SM at 1024 thr
#define WS_OFF    0
#define WS_ROW    65                   // pad-65: scalar LDS banks (e+k)%32
#define BS_OFF    (64 * WS_ROW * 4)    // 16640
#define CS_OFF    (BS_OFF + 256)       // 16896 (16B aligned)
#define CS_ROW    68
#define SMEM_TOTAL KS_BYTES

__device__ __forceinline__ unsigned h2u(__half2 h) { return *reinterpret_cast<unsigned*>(&h); }
__device__ __forceinline__ __half2 u2h(unsigned u) { return *reinterpret_cast<__half2*>(&u); }

__device__ __forceinline__ __half2 h2ex2(__half2 v) {
    unsigned r, a = h2u(v);
    asm("ex2.approx.f16x2 %0, %1;" : "=r"(r) : "r"(a));
    return u2h(r);
}

// ---------------------------------------------------------------------------
// One kernel: block = (b, 16-query chunk), all 8 heads. 256 blocks x 1024 thr
// -> 2 blocks/SM, ~55 warps/SM (vs 27.7 at 512 thr): covers the LDS->HFMA2->
// EX2 chain latency that has pinned issue at ~50% for four rounds.
// ---------------------------------------------------------------------------
__global__ void __launch_bounds__(NT, 2) fused_kernel(
    const float* __restrict__ x,      // [B, S, E]
    const float* __restrict__ theta,  // [8]
    const float* __restrict__ W,      // [64, 64] (e, k)
    const float* __restrict__ bo,     // [64]
    float* __restrict__ out)          // [B*S, 64]
{
    extern __shared__ char sm[];

    const int tid   = threadIdx.x;    // 0..1023
    const int bid   = blockIdx.x;     // 0..255
    const int b     = bid >> 5;
    const int chunk = bid & 31;       // 16-query chunk

    float th[8];
#pragma unroll
    for (int j = 0; j < 8; ++j) th[j] = __ldg(theta + j);

    // ---- Phase A: build fp16 K for all 8 heads ----
    const float4* x4 = (const float4*)x + (size_t)b * (S * E / 4);
#pragma unroll
    for (int j = 0; j < 8; ++j) {
        int m = j * NT + tid;         // 0..8191
        int r = m >> 4;               // key row 0..511
        int c = m & 15;               // float4 chunk; head = c>>1
        float4 v = __ldg(x4 + m);
        int tb = (c & 1) * 4;
        float f0 = __cosf(v.x + th[tb + 0]);
        float f1 = __cosf(v.y + th[tb + 1]);
        float f2 = __cosf(v.z + th[tb + 2]);
        float f3 = __cosf(v.w + th[tb + 3]);
        float g0 = __shfl_xor_sync(0xffffffffu, f0, 1);
        float g1 = __shfl_xor_sync(0xffffffffu, f1, 1);
        float g2 = __shfl_xor_sync(0xffffffffu, f2, 1);
        float g3 = __shfl_xor_sync(0xffffffffu, f3, 1);
        bool hi = (c & 1);
        float c0 = hi ? g0 : f0, c1 = hi ? g1 : f1;
        float c2 = hi ? g2 : f2, c3 = hi ? g3 : f3;
        float c4 = hi ? f0 : g0, c5 = hi ? f1 : g1;
        float c6 = hi ? f2 : g2, c7 = hi ? f3 : g3;
        float q1 = c0 * c1, q2 = q1 * c2, q3 = q2 * c3;
        float q4 = q3 * c4, q5 = q4 * c5, q6 = q5 * c6, q7 = q6 * c7;
        float t01 = c1 * c2, t23 = c3 * c4, t45 = c5 * c6;
        float q0 = t01 * t23 * t45 * c7;
        float a0 = hi ? q4 : q0, a1 = hi ? q5 : q1;
        float a2 = hi ? q6 : q2, a3 = hi ? q7 : q3;
        __half2 p0 = __floats2half2_rn(a0, a1);
        __half2 p1 = __floats2half2_rn(a2, a3);
        char* dst = sm + (c >> 1) * KS_STRIDE + r * 16 + (c & 1) * 8;
        *(uint2*)dst = make_uint2(h2u(p0), h2u(p1));
    }
    __syncthreads();

    // ---- Phase B: attention ----
    // tid = h*128 + qq*8 + g : head h, query qq (0..15), key-split g (0..7).
    // Lanes g=0..7 at 16B row stride hit bank quads {0,4,...,28}: all 32
    // banks covered, conflict-free broadcast LDS.128.
    const int h  = tid >> 7;
    const int rr = tid & 127;
    const int qq = rr >> 3;
    const int g  = rr & 7;
    const int sq = chunk * 16 + qq;   // query's key-row index

    uint4 qv = *(const uint4*)(sm + h * KS_STRIDE + sq * 16);
    const __half2 sch = __float2half2_rn(0.51010202f); // (1/sqrt(8))*log2(e)
    __half2 qh0 = __hmul2(u2h(qv.x), sch);
    __half2 qh1 = __hmul2(u2h(qv.y), sch);
    __half2 qh2 = __hmul2(u2h(qv.z), sch);
    __half2 qh3 = __hmul2(u2h(qv.w), sch);

    const __half2 hz = __float2half2_rn(0.f);
    float F[8] = {0.f, 0.f, 0.f, 0.f, 0.f, 0.f, 0.f, 0.f};
    float lf = 0.f;

    const char* kp = sm + h * KS_STRIDE + g * 16;   // keys s = 8i + g
    for (int o = 0; o < 4; ++o) {
        __half2 a0 = hz, a1 = hz, a2 = hz, a3 = hz, l2 = hz;
        const char* kpo = kp + o * 2048;            // 16 keys * 128B
#pragma unroll
        for (int i = 0; i < 16; ++i) {
            uint4 kv = *(const uint4*)(kpo + i * 128);
            __half2 k0 = u2h(kv.x), k1 = u2h(kv.y), k2 = u2h(kv.z), k3 = u2h(kv.w);
            __half2 d = __hmul2(qh0, k0);
            d = __hfma2(qh1, k1, d);
            d = __hfma2(qh2, k2, d);
            d = __hfma2(qh3, k3, d);
            __half2 ds = __hadd2(d, __lowhigh2highlow(d));
            __half2 w2 = h2ex2(ds);
            l2 = __hadd2(l2, w2);
            a0 = __hfma2(w2, k0, a0);
            a1 = __hfma2(w2, k1, a1);
            a2 = __hfma2(w2, k2, a2);
            a3 = __hfma2(w2, k3, a3);
        }
        float2 t;
        t = __half22float2(a0); F[0] += t.x; F[1] += t.y;
        t = __half22float2(a1); F[2] += t.x; F[3] += t.y;
        t = __half22float2(a2); F[4] += t.x; F[5] += t.y;
        t = __half22float2(a3); F[6] += t.x; F[7] += t.y;
        lf += __low2float(l2);
    }

    // reduce across the 8 split lanes (contiguous within the warp)
    float FF[9] = {F[0], F[1], F[2], F[3], F[4], F[5], F[6], F[7], lf};
#pragma unroll
    for (int v = 0; v < 9; ++v) {
        FF[v] += __shfl_xor_sync(0xffffffffu, FF[v], 1);
        FF[v] += __shfl_xor_sync(0xffffffffu, FF[v], 2);
        FF[v] += __shfl_xor_sync(0xffffffffu, FF[v], 4);
    }

    // ---- K region is dead after this sync; overlay proj staging ----
    __syncthreads();

    float* Ws = (float*)(sm + WS_OFF);
    float* bs = (float*)(sm + BS_OFF);
    float* Cs = (float*)(sm + CS_OFF);

    if (g == 0) {
        float inv = 1.f / FF[8];
        float* cp = Cs + qq * CS_ROW + h * 8;
        *(float4*)(cp + 0) = make_float4(FF[0] * inv, FF[1] * inv, FF[2] * inv, FF[3] * inv);
        *(float4*)(cp + 4) = make_float4(FF[4] * inv, FF[5] * inv, FF[6] * inv, FF[7] * inv);
    }
    // stage W (pad-65 scalar) + bias concurrently with Cs writes
    for (int i = tid; i < 64 * 64; i += NT) {
        int e = i >> 6, k = i & 63;
        Ws[e * WS_ROW + k] = __ldg(W + i);
    }
    if (tid < 64) bs[tid] = __ldg(bo + tid);
    __syncthreads();

    // ---- Phase C: projection, 1 output/thread (16 rows x 64 cols) ----
    {
        const int r = tid >> 6;           // 0..15 (warp-uniform: 2 warps/row)
        const int e = tid & 63;
        const float* crow = Cs + r * CS_ROW;
        float acc = bs[e];
#pragma unroll 8
        for (int k = 0; k < 64; ++k)
            acc = fmaf(crow[k], Ws[e * WS_ROW + k], acc);  // Cs bcast, Ws conflict-free
        const int n = b * S + chunk * 16 + r;
        out[(size_t)n * 64 + e] = acc;
    }
}

extern "C" void kernel_launch(void* const* d_in, const int* in_sizes, int n_in,
                              void* d_out, int out_size)
{
    const float* x     = (const float*)d_in[0];  // [8, 512, 64]
    const float* theta = (const float*)d_in[1];  // [8]
    const float* W_o   = (const float*)d_in[2];  // [64, 64]
    const float* b_o   = (const float*)d_in[3];  // [64]
    float* out = (float*)d_out;

    cudaFuncSetAttribute(fused_kernel,
                         cudaFuncAttributeMaxDynamicSharedMemorySize, SMEM_TOTAL);
    fused_kernel<<<256, NT, SMEM_TOTAL>>>(x, theta, W_o, b_o, out);
}